// round 3
// baseline (speedup 1.0000x reference)
#include <cuda_runtime.h>
#include <math.h>

// Problem constants
#define NB     8
#define LSEQ   144
#define DM     256
#define DI     512
#define DS     64
#define RDT    4
#define NROWS  (NB * LSEQ)          // 1152
#define DBC_W  (RDT + 2 * DS)       // 132

// ---------------------------------------------------------------------------
// Scratch (device globals; allocation-free per harness rules)
// ---------------------------------------------------------------------------
__device__ float  g_xz [NROWS * 1024];   // [row][0:512)=ix pre-conv, [512:1024)=z
__device__ float  g_ix [NROWS * DI];     // after conv + SiLU
__device__ float  g_dBC[NROWS * DBC_W];  // [0:4)=dt_r, [4:68)=B, [68:132)=C
__device__ float2 g_dix[NROWS * DI];     // (delta, ix) packed
__device__ float  g_yz [NROWS * DI];     // (y + Dp*ix) * silu(z)

// ---------------------------------------------------------------------------
// Generic NT GEMM body: C[m,n] = sum_k A[m*K+k] * B[n*K+k]
// BM=BN=64, BK=16, 256 threads, 4x4 microtile. Requires M%64==0, K%16==0.
// N is bounds-checked (needed for N=132).
// ---------------------------------------------------------------------------
__device__ __forceinline__ void gemm_nt_body(
    const float* __restrict__ A, const float* __restrict__ Bm,
    float* __restrict__ C, int N, int K)
{
    __shared__ float As[16][68];
    __shared__ float Bs[16][68];

    const int tid = threadIdx.x;
    const int tx  = tid & 15;
    const int ty  = tid >> 4;
    const int bm  = blockIdx.y * 64;
    const int bn  = blockIdx.x * 64;

    const int lr = tid >> 2;          // 0..63 row within tile
    const int lc = (tid & 3) << 2;    // k offset 0,4,8,12

    const float* Ag = A  + (size_t)(bm + lr) * K + lc;
    const float* Bg = Bm + (size_t)(bn + lr) * K + lc;
    const bool bvalid = (bn + lr) < N;

    float acc[4][4];
#pragma unroll
    for (int i = 0; i < 4; i++)
#pragma unroll
        for (int j = 0; j < 4; j++) acc[i][j] = 0.0f;

    for (int k0 = 0; k0 < K; k0 += 16) {
        float4 av = *(const float4*)(Ag + k0);
        float4 bv = bvalid ? *(const float4*)(Bg + k0) : make_float4(0.f, 0.f, 0.f, 0.f);
        As[lc + 0][lr] = av.x; As[lc + 1][lr] = av.y;
        As[lc + 2][lr] = av.z; As[lc + 3][lr] = av.w;
        Bs[lc + 0][lr] = bv.x; Bs[lc + 1][lr] = bv.y;
        Bs[lc + 2][lr] = bv.z; Bs[lc + 3][lr] = bv.w;
        __syncthreads();
#pragma unroll
        for (int kk = 0; kk < 16; kk++) {
            float4 ra = *(const float4*)(&As[kk][ty << 2]);
            float4 rb = *(const float4*)(&Bs[kk][tx << 2]);
            float a0 = ra.x, a1 = ra.y, a2 = ra.z, a3 = ra.w;
            float b0 = rb.x, b1 = rb.y, b2 = rb.z, b3 = rb.w;
            acc[0][0] = fmaf(a0, b0, acc[0][0]); acc[0][1] = fmaf(a0, b1, acc[0][1]);
            acc[0][2] = fmaf(a0, b2, acc[0][2]); acc[0][3] = fmaf(a0, b3, acc[0][3]);
            acc[1][0] = fmaf(a1, b0, acc[1][0]); acc[1][1] = fmaf(a1, b1, acc[1][1]);
            acc[1][2] = fmaf(a1, b2, acc[1][2]); acc[1][3] = fmaf(a1, b3, acc[1][3]);
            acc[2][0] = fmaf(a2, b0, acc[2][0]); acc[2][1] = fmaf(a2, b1, acc[2][1]);
            acc[2][2] = fmaf(a2, b2, acc[2][2]); acc[2][3] = fmaf(a2, b3, acc[2][3]);
            acc[3][0] = fmaf(a3, b0, acc[3][0]); acc[3][1] = fmaf(a3, b1, acc[3][1]);
            acc[3][2] = fmaf(a3, b2, acc[3][2]); acc[3][3] = fmaf(a3, b3, acc[3][3]);
        }
        __syncthreads();
    }

#pragma unroll
    for (int i = 0; i < 4; i++) {
        const int m = bm + (ty << 2) + i;
#pragma unroll
        for (int j = 0; j < 4; j++) {
            const int n = bn + (tx << 2) + j;
            if (n < N) C[(size_t)m * N + n] = acc[i][j];
        }
    }
}

// gemm1: xz = x @ W_in^T    (M=1152, N=1024, K=256)
__global__ void gemm1_kernel(const float* __restrict__ x,
                             const float* __restrict__ W_in) {
    gemm_nt_body(x, W_in, g_xz, 1024, DM);
}

// gemm_dbc: dBC = ix @ W_x^T (M=1152, N=132, K=512)
__global__ void gemm_dbc_kernel(const float* __restrict__ W_x) {
    gemm_nt_body(g_ix, W_x, g_dBC, DBC_W, DI);
}

// gemm_out: out = yz @ W_out^T (M=1152, N=256, K=512)
__global__ void gemm_out_kernel(const float* __restrict__ W_out,
                                float* __restrict__ out) {
    gemm_nt_body(g_yz, W_out, out, DM, DI);
}

// ---------------------------------------------------------------------------
// Depthwise conv (kernel 4, padding (2,1)) + bias + SiLU
// grid = NROWS blocks, 512 threads (one per channel d)
// ---------------------------------------------------------------------------
__global__ void conv_silu_kernel(const float* __restrict__ conv_w,
                                 const float* __restrict__ conv_b) {
    const int row = blockIdx.x;          // b*144 + l
    const int d   = threadIdx.x;         // 0..511
    const int b   = row / LSEQ;
    const int l   = row - b * LSEQ;

    const float4 w = *(const float4*)(conv_w + 4 * d);
    float acc = conv_b[d];
    const float wk[4] = {w.x, w.y, w.z, w.w};
#pragma unroll
    for (int k = 0; k < 4; k++) {
        const int ls = l - 2 + k;
        if (ls >= 0 && ls < LSEQ)
            acc = fmaf(g_xz[(size_t)(b * LSEQ + ls) * 1024 + d], wk[k], acc);
    }
    // SiLU
    const float s = acc * __fdividef(1.0f, 1.0f + __expf(-acc));
    g_ix[(size_t)row * DI + d] = s;
}

// ---------------------------------------------------------------------------
// delta = softplus(dt_r @ W_dt^T + b_dt); pack (delta, ix) as float2
// grid = NROWS blocks, 512 threads
// ---------------------------------------------------------------------------
__global__ void delta_kernel(const float* __restrict__ W_dt,
                             const float* __restrict__ b_dt) {
    const int row = blockIdx.x;
    const int d   = threadIdx.x;

    const float* dtr = g_dBC + (size_t)row * DBC_W;   // first 4 = dt_r (uniform)
    const float4 wd = *(const float4*)(W_dt + 4 * d);
    float v = b_dt[d];
    v = fmaf(dtr[0], wd.x, v);
    v = fmaf(dtr[1], wd.y, v);
    v = fmaf(dtr[2], wd.z, v);
    v = fmaf(dtr[3], wd.w, v);
    const float delta = (v > 20.0f) ? v : log1pf(expf(v));   // accurate softplus
    const float ix = g_ix[(size_t)row * DI + d];
    g_dix[(size_t)row * DI + d] = make_float2(delta, ix);
}

// ---------------------------------------------------------------------------
// Selective scan: one warp per (b, d), lane owns states {2*lane, 2*lane+1}.
// 4096 warps total. Fuses y = scan + Dp*ix, then * silu(z) into g_yz.
// ---------------------------------------------------------------------------
__global__ void scan_kernel(const float* __restrict__ A_log,
                            const float* __restrict__ Dp) {
    const int gwarp = (blockIdx.x * blockDim.x + threadIdx.x) >> 5;
    const int lane  = threadIdx.x & 31;
    const int b = gwarp >> 9;          // / 512
    const int d = gwarp & 511;
    const int n0 = lane << 1;

    const float A0 = -expf(A_log[d * DS + n0]);
    const float A1 = -expf(A_log[d * DS + n0 + 1]);
    const float Dpd = Dp[d];

    float h0 = 0.0f, h1 = 0.0f;
    const int rowbase = b * LSEQ;

    for (int t = 0; t < LSEQ; t++) {
        const int row = rowbase + t;
        const float2 di = g_dix[(size_t)row * DI + d];        // uniform broadcast
        const float* pr = g_dBC + (size_t)row * DBC_W;
        const float2 Bv = *(const float2*)(pr + RDT + n0);        // B[n0], B[n0+1]
        const float2 Cv = *(const float2*)(pr + RDT + DS + n0);   // C[n0], C[n0+1]

        const float dix = di.x * di.y;
        const float dA0 = __expf(di.x * A0);
        const float dA1 = __expf(di.x * A1);
        h0 = fmaf(dA0, h0, dix * Bv.x);
        h1 = fmaf(dA1, h1, dix * Bv.y);

        float p = fmaf(h0, Cv.x, h1 * Cv.y);
#pragma unroll
        for (int o = 16; o > 0; o >>= 1)
            p += __shfl_xor_sync(0xffffffffu, p, o);

        if (lane == 0) {
            const float y  = fmaf(Dpd, di.y, p);
            const float zv = g_xz[(size_t)row * 1024 + DI + d];
            const float sz = zv * __fdividef(1.0f, 1.0f + __expf(-zv));
            g_yz[(size_t)row * DI + d] = y * sz;
        }
    }
}

// ---------------------------------------------------------------------------
// Launch: 6 graph-capturable kernels on the default stream
// ---------------------------------------------------------------------------
extern "C" void kernel_launch(void* const* d_in, const int* in_sizes, int n_in,
                              void* d_out, int out_size) {
    const float* x      = (const float*)d_in[0];
    // d_in[1] = lastin (zeros, unused: h0 = 0)
    const float* W_in   = (const float*)d_in[2];
    const float* conv_w = (const float*)d_in[3];
    const float* conv_b = (const float*)d_in[4];
    const float* W_x    = (const float*)d_in[5];
    const float* W_dt   = (const float*)d_in[6];
    const float* b_dt   = (const float*)d_in[7];
    const float* A_log  = (const float*)d_in[8];
    const float* Dp     = (const float*)d_in[9];
    const float* W_out  = (const float*)d_in[10];
    float* out = (float*)d_out;

    // 1) xz = x @ W_in^T
    gemm1_kernel<<<dim3(1024 / 64, NROWS / 64), 256>>>(x, W_in);
    // 2) depthwise conv + SiLU
    conv_silu_kernel<<<NROWS, DI>>>(conv_w, conv_b);
    // 3) dBC = ix @ W_x^T
    gemm_dbc_kernel<<<dim3((DBC_W + 63) / 64, NROWS / 64), 256>>>(W_x);
    // 4) delta + pack
    delta_kernel<<<NROWS, DI>>>(W_dt, b_dt);
    // 5) selective scan (+ Dp*ix, * silu(z))
    scan_kernel<<<512, 256>>>(A_log, Dp);
    // 6) out = yz @ W_out^T
    gemm_out_kernel<<<dim3(DM / 64, NROWS / 64), 256>>>(W_out, out);
}